// round 1
// baseline (speedup 1.0000x reference)
#include <cuda_runtime.h>
#include <cstdint>

// ---------------------------------------------------------------------------
// FP4 block quant-dequant, BLOCK=64, scale = 95th pct of |x| per block,
// double-quantized scales (global min/max over blocks).
//
// Pipeline (graph-capturable, no allocs):
//   k_init  : reset global scale min/max          (must run every replay)
//   k_pass1 : x -> per-block scale + 4-bit codes, atomic min/max of scales
//   k_prep  : scale_scale + reciprocal (1 thread)
//   k_pass2 : codes -> dequantized output
// ---------------------------------------------------------------------------

#define NBLK_CAP 262144   // 16777216 / 64

__device__ float    g_scales[NBLK_CAP];
__device__ uint4    g_codes[NBLK_CAP * 2];   // 32 bytes of codes per block
__device__ unsigned g_smin_bits;
__device__ unsigned g_smax_bits;
__device__ float    g_smin_f;
__device__ float    g_ss;    // scale_scale
__device__ float    g_iss;   // 1/scale_scale

__global__ void k_init() {
    g_smin_bits = 0x7F800000u;  // +inf
    g_smax_bits = 0u;
}

// Branchless insert of v (>=0) into descending top-5 (t0 >= t1 >= ... >= t4).
__device__ __forceinline__ void ins5(float& t0, float& t1, float& t2,
                                     float& t3, float& t4, float v) {
    float a;
    a = fminf(t0, v); t0 = fmaxf(t0, v);
    float b = fminf(t1, a); t1 = fmaxf(t1, a);
    a = fminf(t2, b); t2 = fmaxf(t2, b);
    b = fminf(t3, a); t3 = fmaxf(t3, a);
    t4 = fmaxf(t4, b);
}

// Quantize one element to a 4-bit code: bit3 = sign, bits[2:0] = level 0..5
// (magnitudes 0, 0.75, 1, 1.5, 2, 3).
// Reproduces jnp argmin over the sorted table exactly:
//   x>=0 : strict  >  against midpoints (tie -> lower level, lower index)
//   x<0  : >= against midpoints (tie -> larger magnitude, lower index),
//          implemented exactly as a > nextafter_down(midpoint).
// r = fl(x/s) via per-block reciprocal + one FMA Newton correction
// (correctly rounded except a ~2^-28 relative window).
__device__ __forceinline__ unsigned quant1(float xx, float s, float sinv) {
    float r0 = xx * sinv;
    float r  = fmaf(fmaf(-s, r0, xx), sinv, r0);
    float a  = fabsf(r);
    bool neg = xx < 0.0f;
    float T0 = neg ? __uint_as_float(0x3EBFFFFFu) : 0.375f;
    float T1 = neg ? __uint_as_float(0x3F5FFFFFu) : 0.875f;
    float T2 = neg ? __uint_as_float(0x3F9FFFFFu) : 1.25f;
    float T3 = neg ? __uint_as_float(0x3FDFFFFFu) : 1.75f;
    float T4 = neg ? __uint_as_float(0x401FFFFFu) : 2.5f;
    unsigned k = (unsigned)(a > T0) + (unsigned)(a > T1) + (unsigned)(a > T2)
               + (unsigned)(a > T3) + (unsigned)(a > T4);
    return k | (neg ? 8u : 0u);
}

__global__ void __launch_bounds__(256) k_pass1(const float* __restrict__ x,
                                               int nblocks, int n) {
    int b = blockIdx.x * 256 + threadIdx.x;
    bool valid = b < nblocks;

    float vmn = __uint_as_float(0x7F800000u);
    float vmx = 0.0f;

    if (valid) {
        float4 vals[16];
        long base = (long)b * 64;
        if (base + 64 <= (long)n) {
            const float4* xv = reinterpret_cast<const float4*>(x + base);
            #pragma unroll
            for (int i = 0; i < 16; i++) vals[i] = xv[i];
        } else {
            // tail block: zero-pad (matches reference padding)
            #pragma unroll
            for (int i = 0; i < 16; i++) {
                float4 v;
                v.x = (base + i * 4 + 0 < (long)n) ? x[base + i * 4 + 0] : 0.0f;
                v.y = (base + i * 4 + 1 < (long)n) ? x[base + i * 4 + 1] : 0.0f;
                v.z = (base + i * 4 + 2 < (long)n) ? x[base + i * 4 + 2] : 0.0f;
                v.w = (base + i * 4 + 3 < (long)n) ? x[base + i * 4 + 3] : 0.0f;
                vals[i] = v;
            }
        }

        // top-5 of |x| over the block
        float t0 = 0.f, t1 = 0.f, t2 = 0.f, t3 = 0.f, t4 = 0.f;
        #pragma unroll
        for (int i = 0; i < 16; i++) {
            ins5(t0, t1, t2, t3, t4, fabsf(vals[i].x));
            ins5(t0, t1, t2, t3, t4, fabsf(vals[i].y));
            ins5(t0, t1, t2, t3, t4, fabsf(vals[i].z));
            ins5(t0, t1, t2, t3, t4, fabsf(vals[i].w));
        }

        // 95th percentile, linear interp: index = 0.95*(64-1)
        // sorted[59] = t4 (5th largest), sorted[60] = t3 (4th largest)
        const float idxf = 0.95f * 63.0f;   // f32, matches jnp
        const float hw   = idxf - 59.0f;    // exact
        const float lw   = 1.0f - hw;       // exact
        float s = t4 * lw + t3 * hw;
        s = fmaxf(s, 1e-8f);
        g_scales[b] = s;
        vmn = s; vmx = s;

        float sinv = 1.0f / s;  // correctly-rounded, once per block

        unsigned w[8];
        #pragma unroll
        for (int i = 0; i < 8; i++) w[i] = 0u;
        #pragma unroll
        for (int i = 0; i < 16; i++) {
            unsigned nib =  quant1(vals[i].x, s, sinv)
                         | (quant1(vals[i].y, s, sinv) << 4)
                         | (quant1(vals[i].z, s, sinv) << 8)
                         | (quant1(vals[i].w, s, sinv) << 12);
            w[i >> 1] |= nib << ((i & 1) * 16);
        }
        g_codes[(size_t)b * 2 + 0] = make_uint4(w[0], w[1], w[2], w[3]);
        g_codes[(size_t)b * 2 + 1] = make_uint4(w[4], w[5], w[6], w[7]);
    }

    // CTA reduce of scale min/max, then one atomic pair per CTA.
    #pragma unroll
    for (int o = 16; o > 0; o >>= 1) {
        vmn = fminf(vmn, __shfl_xor_sync(0xFFFFFFFFu, vmn, o));
        vmx = fmaxf(vmx, __shfl_xor_sync(0xFFFFFFFFu, vmx, o));
    }
    __shared__ float shm[8], shx[8];
    int wid = threadIdx.x >> 5;
    if ((threadIdx.x & 31) == 0) { shm[wid] = vmn; shx[wid] = vmx; }
    __syncthreads();
    if (threadIdx.x == 0) {
        float mn = shm[0], mx = shx[0];
        #pragma unroll
        for (int i = 1; i < 8; i++) {
            mn = fminf(mn, shm[i]);
            mx = fmaxf(mx, shx[i]);
        }
        // scales are strictly positive -> uint-bit ordering == float ordering
        atomicMin(&g_smin_bits, __float_as_uint(mn));
        atomicMax(&g_smax_bits, __float_as_uint(mx));
    }
}

__global__ void k_prep() {
    float smin = __uint_as_float(g_smin_bits);
    float smax = __uint_as_float(g_smax_bits);
    float ss = (smax > smin) ? (smax - smin) / 255.0f : 1.0f;
    g_smin_f = smin;
    g_ss  = ss;
    g_iss = 1.0f / ss;
}

// Decode one 4-bit code to its FP4 level value times ds.
// k=0..5 -> magnitude {0, 0.75, 1, 1.5, 2, 3} built directly as float bits:
// exp = 126 + (k>>1), mantissa-top = k&1 (k>0); bit3 of code -> sign.
__device__ __forceinline__ float dec1(unsigned c, float ds) {
    unsigned k  = c & 7u;
    unsigned eb = ((126u + (k >> 1)) << 23) | ((k & 1u) << 22);
    eb = k ? eb : 0u;
    eb |= (c & 8u) << 28;  // sign bit
    return __uint_as_float(eb) * ds;
}

__global__ void __launch_bounds__(256) k_pass2(float* __restrict__ out,
                                               int nblocks, int n) {
    int b = blockIdx.x * 256 + threadIdx.x;
    if (b >= nblocks) return;

    float s    = g_scales[b];
    float smin = g_smin_f;
    float ss   = g_ss;
    float iss  = g_iss;

    // q = round((s - smin)/ss) half-to-even, matching jnp.round; refined
    // reciprocal multiply reproduces the correctly-rounded division.
    float d  = s - smin;
    float q0 = d * iss;
    float q  = fmaf(fmaf(-ss, q0, d), iss, q0);
    q = rintf(q);
    q = fminf(fmaxf(q, 0.0f), 255.0f);
    float ds = q * ss;   // NOTE: reference drops smin in dequant (faithful)

    uint4 w0 = g_codes[(size_t)b * 2 + 0];
    uint4 w1 = g_codes[(size_t)b * 2 + 1];
    unsigned ws[8] = {w0.x, w0.y, w0.z, w0.w, w1.x, w1.y, w1.z, w1.w};

    long base = (long)b * 64;
    if (base + 64 <= (long)n) {
        float4* ov = reinterpret_cast<float4*>(out + base);
        #pragma unroll
        for (int i = 0; i < 8; i++) {
            unsigned w = ws[i];
            float4 o;
            o.x = dec1( w         & 15u, ds);
            o.y = dec1((w >>  4) & 15u, ds);
            o.z = dec1((w >>  8) & 15u, ds);
            o.w = dec1((w >> 12) & 15u, ds);
            ov[i * 2 + 0] = o;
            o.x = dec1((w >> 16) & 15u, ds);
            o.y = dec1((w >> 20) & 15u, ds);
            o.z = dec1((w >> 24) & 15u, ds);
            o.w = dec1((w >> 28) & 15u, ds);
            ov[i * 2 + 1] = o;
        }
    } else {
        for (int j = 0; j < 64; j++) {
            long idx = base + j;
            if (idx < (long)n)
                out[idx] = dec1((ws[j >> 3] >> ((j & 7) * 4)) & 15u, ds);
        }
    }
}

extern "C" void kernel_launch(void* const* d_in, const int* in_sizes, int n_in,
                              void* d_out, int out_size) {
    const float* x = (const float*)d_in[0];
    int n = in_sizes[0];
    int nblocks = (n + 63) / 64;
    int grid = (nblocks + 255) / 256;

    k_init<<<1, 1>>>();
    k_pass1<<<grid, 256>>>(x, nblocks, n);
    k_prep<<<1, 1>>>();
    k_pass2<<<grid, 256>>>((float*)d_out, nblocks, n);
}

// round 2
// speedup vs baseline: 1.2055x; 1.2055x over previous
#include <cuda_runtime.h>
#include <cstdint>

// ---------------------------------------------------------------------------
// FP4 block quant-dequant, BLOCK=64, scale = 95th pct of |x| per block,
// double-quantized scales (global min/max over blocks).
//
//   k_init  : reset global scale min/max          (must run every replay)
//   k_pass1 : x -> per-block scale + 4-bit codes (smem-staged, coalesced)
//   k_prep  : scale_scale params (1 thread)
//   k_pass2 : codes -> dequantized output (thread-per-float4, coalesced)
// ---------------------------------------------------------------------------

#define NBLK_CAP 262144   // 16777216 / 64
#define P1_THREADS 128
#define BLK_PER_CTA 128

__device__ float    g_scales[NBLK_CAP];
__device__ unsigned g_codes32[NBLK_CAP * 8];  // 8 u32 per block, element order
__device__ unsigned g_smin_bits;
__device__ unsigned g_smax_bits;
__device__ float4   g_params;                 // {smin, ss, 1/ss, 0}

__global__ void k_init() {
    g_smin_bits = 0x7F800000u;  // +inf
    g_smax_bits = 0u;
}

// Branchless insert of v (>=0) into descending top-5 (t0 >= ... >= t4).
__device__ __forceinline__ void ins5(float& t0, float& t1, float& t2,
                                     float& t3, float& t4, float v) {
    float a;
    a = fminf(t0, v); t0 = fmaxf(t0, v);
    float b = fminf(t1, a); t1 = fmaxf(t1, a);
    a = fminf(t2, b); t2 = fmaxf(t2, b);
    b = fminf(t3, a); t3 = fmaxf(t3, a);
    t4 = fmaxf(t4, b);
}

// 4-bit code: bit3 = sign, bits[2:0] = level 0..5 (mags 0,0.75,1,1.5,2,3).
// Reproduces jnp argmin over the sorted table:
//   x>=0 : strict >  against midpoints; x<0 : >= (== > nextafter_down(mid)).
// fl(x/s) via per-block reciprocal + one FMA Newton correction.
__device__ __forceinline__ unsigned quant1(float xx, float s, float sinv) {
    float r0 = xx * sinv;
    float r  = fmaf(fmaf(-s, r0, xx), sinv, r0);
    float a  = fabsf(r);
    bool neg = xx < 0.0f;
    float T0 = neg ? __uint_as_float(0x3EBFFFFFu) : 0.375f;
    float T1 = neg ? __uint_as_float(0x3F5FFFFFu) : 0.875f;
    float T2 = neg ? __uint_as_float(0x3F9FFFFFu) : 1.25f;
    float T3 = neg ? __uint_as_float(0x3FDFFFFFu) : 1.75f;
    float T4 = neg ? __uint_as_float(0x401FFFFFu) : 2.5f;
    unsigned k = (unsigned)(a > T0) + (unsigned)(a > T1) + (unsigned)(a > T2)
               + (unsigned)(a > T3) + (unsigned)(a > T4);
    return k | (neg ? 8u : 0u);
}

__global__ void __launch_bounds__(P1_THREADS) k_pass1(const float* __restrict__ x,
                                                      int nblocks, int n) {
    // Stage 128 blocks (32KB) coalesced; row stride 17 float4s kills
    // bank conflicts on the per-thread strided re-read.
    __shared__ float4 sm[BLK_PER_CTA * 17];

    int tid = threadIdx.x;
    int cta_blk0 = blockIdx.x * BLK_PER_CTA;
    long base4 = (long)cta_blk0 * 16;       // float4 index of CTA's data
    const float4* x4 = reinterpret_cast<const float4*>(x);
    bool full = (base4 + BLK_PER_CTA * 16) * 4 <= (long)n;

    #pragma unroll
    for (int k = 0; k < 16; k++) {
        int l4 = tid + k * P1_THREADS;      // 0..2047
        float4 v;
        if (full) {
            v = x4[base4 + l4];
        } else {
            long e = (base4 + l4) * 4;
            v.x = (e + 0 < (long)n) ? x[e + 0] : 0.0f;
            v.y = (e + 1 < (long)n) ? x[e + 1] : 0.0f;
            v.z = (e + 2 < (long)n) ? x[e + 2] : 0.0f;
            v.w = (e + 3 < (long)n) ? x[e + 3] : 0.0f;
        }
        sm[(l4 >> 4) * 17 + (l4 & 15)] = v;
    }
    __syncthreads();

    int b = cta_blk0 + tid;
    bool valid = b < nblocks;
    float vmn = __uint_as_float(0x7F800000u);
    float vmx = 0.0f;

    if (valid) {
        float4 vals[16];
        #pragma unroll
        for (int i = 0; i < 16; i++) vals[i] = sm[tid * 17 + i];

        float t0 = 0.f, t1 = 0.f, t2 = 0.f, t3 = 0.f, t4 = 0.f;
        #pragma unroll
        for (int i = 0; i < 16; i++) {
            ins5(t0, t1, t2, t3, t4, fabsf(vals[i].x));
            ins5(t0, t1, t2, t3, t4, fabsf(vals[i].y));
            ins5(t0, t1, t2, t3, t4, fabsf(vals[i].z));
            ins5(t0, t1, t2, t3, t4, fabsf(vals[i].w));
        }

        // 95th pct linear interp: idx = 0.95*63 -> between sorted[59]=t4,
        // sorted[60]=t3.
        const float idxf = 0.95f * 63.0f;
        const float hw   = idxf - 59.0f;
        const float lw   = 1.0f - hw;
        float s = t4 * lw + t3 * hw;
        s = fmaxf(s, 1e-8f);
        g_scales[b] = s;
        vmn = s; vmx = s;

        float sinv = 1.0f / s;

        unsigned w[8];
        #pragma unroll
        for (int i = 0; i < 8; i++) w[i] = 0u;
        #pragma unroll
        for (int i = 0; i < 16; i++) {
            unsigned nib =  quant1(vals[i].x, s, sinv)
                         | (quant1(vals[i].y, s, sinv) << 4)
                         | (quant1(vals[i].z, s, sinv) << 8)
                         | (quant1(vals[i].w, s, sinv) << 12);
            w[i >> 1] |= nib << ((i & 1) * 16);
        }
        uint4* c4 = reinterpret_cast<uint4*>(g_codes32);
        c4[(size_t)b * 2 + 0] = make_uint4(w[0], w[1], w[2], w[3]);
        c4[(size_t)b * 2 + 1] = make_uint4(w[4], w[5], w[6], w[7]);
    }

    // warp + CTA reduce of scale min/max, one atomic pair per CTA
    #pragma unroll
    for (int o = 16; o > 0; o >>= 1) {
        vmn = fminf(vmn, __shfl_xor_sync(0xFFFFFFFFu, vmn, o));
        vmx = fmaxf(vmx, __shfl_xor_sync(0xFFFFFFFFu, vmx, o));
    }
    __shared__ float shm[4], shx[4];
    int wid = tid >> 5;
    if ((tid & 31) == 0) { shm[wid] = vmn; shx[wid] = vmx; }
    __syncthreads();
    if (tid == 0) {
        float mn = shm[0], mx = shx[0];
        #pragma unroll
        for (int i = 1; i < 4; i++) {
            mn = fminf(mn, shm[i]);
            mx = fmaxf(mx, shx[i]);
        }
        atomicMin(&g_smin_bits, __float_as_uint(mn));
        atomicMax(&g_smax_bits, __float_as_uint(mx));
    }
}

__global__ void k_prep() {
    float smin = __uint_as_float(g_smin_bits);
    float smax = __uint_as_float(g_smax_bits);
    float ss = (smax > smin) ? (smax - smin) / 255.0f : 1.0f;
    g_params = make_float4(smin, ss, 1.0f / ss, 0.0f);
}

// Decode 4-bit code: exp = 126 + (k>>1), mantissa-top = k&1 (k>0);
// bit3 -> sign. Multiplied by ds.
__device__ __forceinline__ float dec1(unsigned c, float ds) {
    unsigned k  = c & 7u;
    unsigned eb = ((126u + (k >> 1)) << 23) | ((k & 1u) << 22);
    eb = k ? eb : 0u;
    eb |= (c & 8u) << 28;
    return __uint_as_float(eb) * ds;
}

__global__ void __launch_bounds__(256) k_pass2(float* __restrict__ out, int n) {
    int p4 = blockIdx.x * 256 + threadIdx.x;
    long e0 = (long)p4 * 4;
    if (e0 >= (long)n) return;

    int blk = p4 >> 4;
    float s = g_scales[blk];
    float4 P = g_params;

    // q = round((s - smin)/ss) half-to-even (rintf == jnp.round)
    float d  = s - P.x;
    float q0 = d * P.z;
    float q  = fmaf(fmaf(-P.y, q0, d), P.z, q0);
    q = rintf(q);
    q = fminf(fmaxf(q, 0.0f), 255.0f);
    float ds = q * P.y;   // reference drops smin in dequant (faithful)

    unsigned cw  = g_codes32[p4 >> 1];
    unsigned nib = cw >> ((p4 & 1) * 16);

    float4 o;
    o.x = dec1( nib        & 15u, ds);
    o.y = dec1((nib >>  4) & 15u, ds);
    o.z = dec1((nib >>  8) & 15u, ds);
    o.w = dec1((nib >> 12) & 15u, ds);

    if (e0 + 4 <= (long)n) {
        reinterpret_cast<float4*>(out)[p4] = o;
    } else {
        out[e0] = o.x;
        if (e0 + 1 < (long)n) out[e0 + 1] = o.y;
        if (e0 + 2 < (long)n) out[e0 + 2] = o.z;
    }
}

extern "C" void kernel_launch(void* const* d_in, const int* in_sizes, int n_in,
                              void* d_out, int out_size) {
    const float* x = (const float*)d_in[0];
    int n = in_sizes[0];
    int nblocks = (n + 63) / 64;
    int grid1 = (nblocks + BLK_PER_CTA - 1) / BLK_PER_CTA;
    int n4 = (n + 3) / 4;
    int grid2 = (n4 + 255) / 256;

    k_init<<<1, 1>>>();
    k_pass1<<<grid1, P1_THREADS>>>(x, nblocks, n);
    k_prep<<<1, 1>>>();
    k_pass2<<<grid2, 256>>>((float*)d_out, n);
}

// round 3
// speedup vs baseline: 1.4701x; 1.2195x over previous
#include <cuda_runtime.h>
#include <cstdint>

// ---------------------------------------------------------------------------
// FP4 block quant-dequant, BLOCK=64, scale = 95th pct of |x| per block,
// double-quantized scales (global min/max over blocks).
//
//   k_init  : reset global scale min/max            (every replay)
//   k_pass1 : x -> per-block scale + 4-bit codes (smem-staged, coalesced;
//             per-block premultiplied thresholds — no per-element division)
//   k_ds    : per-block dequant scale ds = q*ss     (scale_scale inline)
//   k_pass2 : codes -> output (thread-per-float4, DRAM-bound)
// ---------------------------------------------------------------------------

#define NBLK_CAP 262144   // 16777216 / 64
#define P1_THREADS 128
#define BLK_PER_CTA 128

__device__ float    g_scales[NBLK_CAP];
__device__ float    g_ds[NBLK_CAP];
__device__ unsigned g_codes32[NBLK_CAP * 8];  // 8 u32 per block, element order
__device__ unsigned g_smin_bits;
__device__ unsigned g_smax_bits;

__global__ void k_init() {
    g_smin_bits = 0x7F800000u;  // +inf
    g_smax_bits = 0u;
}

// Branchless insert of v (>=0) into descending top-5 (t0 >= ... >= t4).
__device__ __forceinline__ void ins5(float& t0, float& t1, float& t2,
                                     float& t3, float& t4, float v) {
    float a;
    a = fminf(t0, v); t0 = fmaxf(t0, v);
    float b = fminf(t1, a); t1 = fmaxf(t1, a);
    a = fminf(t2, b); t2 = fmaxf(t2, b);
    b = fminf(t3, a); t3 = fmaxf(t3, a);
    t4 = fmaxf(t4, b);
}

// Quantize one element against per-block premultiplied midpoints C[5]
// (uint bit patterns of s*{0.375,0.875,1.25,1.75,2.5}).
// For positive floats, uint compare == float compare.
// Code: bit3 = sign, bits[2:0] = level index 0..5.
__device__ __forceinline__ unsigned quant1(float xx, const unsigned* C) {
    unsigned bits = __float_as_uint(xx);
    unsigned mag  = bits & 0x7FFFFFFFu;
    unsigned k = (unsigned)(mag > C[0]) + (unsigned)(mag > C[1])
               + (unsigned)(mag > C[2]) + (unsigned)(mag > C[3])
               + (unsigned)(mag > C[4]);
    return k | ((bits >> 28) & 8u);
}

__global__ void __launch_bounds__(P1_THREADS) k_pass1(const float* __restrict__ x,
                                                      int nblocks, int n) {
    // Stage 128 blocks (32KB) coalesced; row stride 17 float4s keeps the
    // per-thread LDS.128 re-reads bank-conflict-free (quarter-warp phases).
    __shared__ float4 sm[BLK_PER_CTA * 17];

    int tid = threadIdx.x;
    int cta_blk0 = blockIdx.x * BLK_PER_CTA;
    long base4 = (long)cta_blk0 * 16;
    const float4* x4 = reinterpret_cast<const float4*>(x);
    bool full = (base4 + BLK_PER_CTA * 16) * 4 <= (long)n;

    #pragma unroll
    for (int k = 0; k < 16; k++) {
        int l4 = tid + k * P1_THREADS;
        float4 v;
        if (full) {
            v = x4[base4 + l4];
        } else {
            long e = (base4 + l4) * 4;
            v.x = (e + 0 < (long)n) ? x[e + 0] : 0.0f;
            v.y = (e + 1 < (long)n) ? x[e + 1] : 0.0f;
            v.z = (e + 2 < (long)n) ? x[e + 2] : 0.0f;
            v.w = (e + 3 < (long)n) ? x[e + 3] : 0.0f;
        }
        sm[(l4 >> 4) * 17 + (l4 & 15)] = v;
    }
    __syncthreads();

    int b = cta_blk0 + tid;
    bool valid = b < nblocks;
    float vmn = __uint_as_float(0x7F800000u);
    float vmx = 0.0f;

    if (valid) {
        // ---- phase 1: top-5 of |x| (smem re-read, no register blowup) ----
        float t0 = 0.f, t1 = 0.f, t2 = 0.f, t3 = 0.f, t4 = 0.f;
        #pragma unroll
        for (int i = 0; i < 16; i++) {
            float4 v = sm[tid * 17 + i];
            ins5(t0, t1, t2, t3, t4, fabsf(v.x));
            ins5(t0, t1, t2, t3, t4, fabsf(v.y));
            ins5(t0, t1, t2, t3, t4, fabsf(v.z));
            ins5(t0, t1, t2, t3, t4, fabsf(v.w));
        }

        // 95th pct linear interp: idx = 0.95*63 between sorted[59]=t4,
        // sorted[60]=t3.
        const float idxf = 0.95f * 63.0f;
        const float hw   = idxf - 59.0f;
        const float lw   = 1.0f - hw;
        float s = t4 * lw + t3 * hw;
        s = fmaxf(s, 1e-8f);
        g_scales[b] = s;
        vmn = s; vmx = s;

        // premultiplied decision thresholds (once per block)
        unsigned C[5];
        C[0] = __float_as_uint(s * 0.375f);
        C[1] = __float_as_uint(s * 0.875f);
        C[2] = __float_as_uint(s * 1.25f);
        C[3] = __float_as_uint(s * 1.75f);
        C[4] = __float_as_uint(s * 2.5f);

        // ---- phase 2: quantize + pack ----
        unsigned w[8];
        #pragma unroll
        for (int i = 0; i < 16; i++) {
            float4 v = sm[tid * 17 + i];
            unsigned nib =  quant1(v.x, C)
                         | (quant1(v.y, C) << 4)
                         | (quant1(v.z, C) << 8)
                         | (quant1(v.w, C) << 12);
            if (i & 1) w[i >> 1] |= nib << 16;
            else       w[i >> 1]  = nib;
        }
        uint4* c4 = reinterpret_cast<uint4*>(g_codes32);
        c4[(size_t)b * 2 + 0] = make_uint4(w[0], w[1], w[2], w[3]);
        c4[(size_t)b * 2 + 1] = make_uint4(w[4], w[5], w[6], w[7]);
    }

    // warp + CTA reduce of scale min/max, one atomic pair per CTA
    #pragma unroll
    for (int o = 16; o > 0; o >>= 1) {
        vmn = fminf(vmn, __shfl_xor_sync(0xFFFFFFFFu, vmn, o));
        vmx = fmaxf(vmx, __shfl_xor_sync(0xFFFFFFFFu, vmx, o));
    }
    __shared__ float shm[4], shx[4];
    int wid = tid >> 5;
    if ((tid & 31) == 0) { shm[wid] = vmn; shx[wid] = vmx; }
    __syncthreads();
    if (tid == 0) {
        float mn = shm[0], mx = shx[0];
        #pragma unroll
        for (int i = 1; i < 4; i++) {
            mn = fminf(mn, shm[i]);
            mx = fmaxf(mx, shx[i]);
        }
        // scales strictly positive -> uint ordering == float ordering
        atomicMin(&g_smin_bits, __float_as_uint(mn));
        atomicMax(&g_smax_bits, __float_as_uint(mx));
    }
}

// Per-block dequant scale: ds = round((s-smin)/ss) * ss, ss = (smax-smin)/255.
// (Reference drops smin in dequant — faithful.)
__global__ void __launch_bounds__(256) k_ds(int nblocks) {
    int b = blockIdx.x * 256 + threadIdx.x;
    if (b >= nblocks) return;
    float smin = __uint_as_float(g_smin_bits);
    float smax = __uint_as_float(g_smax_bits);
    bool cond = smax > smin;
    float ss  = cond ? (smax - smin) / 255.0f : 1.0f;
    float iss = 1.0f / ss;
    float s = g_scales[b];
    float d  = s - smin;
    float q0 = d * iss;
    float q  = fmaf(fmaf(-ss, q0, d), iss, q0);  // refined == fl(d/ss)
    q = rintf(q);                                // half-to-even == jnp.round
    q = fminf(fmaxf(q, 0.0f), 255.0f);
    if (!cond) q = 0.0f;
    g_ds[b] = q * ss;
}

// Decode 4-bit code: level magnitudes {0,0.75,1,1.5,2,3} are linear in the
// fp32 exponent/mantissa bits: eb = 0x3F000000 + (k<<22), k>0; bit3 -> sign.
__device__ __forceinline__ float dec1(unsigned c, float ds) {
    unsigned k  = c & 7u;
    unsigned eb = 0x3F000000u + (k << 22);
    eb = k ? eb : 0u;
    eb |= (c & 8u) << 28;
    return __uint_as_float(eb) * ds;
}

__global__ void __launch_bounds__(256) k_pass2(float* __restrict__ out, int n) {
    int p4 = blockIdx.x * 256 + threadIdx.x;
    long e0 = (long)p4 * 4;
    if (e0 >= (long)n) return;

    float ds = g_ds[p4 >> 4];
    unsigned cw  = g_codes32[p4 >> 1];
    unsigned nib = cw >> ((p4 & 1) * 16);

    float4 o;
    o.x = dec1( nib        & 15u, ds);
    o.y = dec1((nib >>  4) & 15u, ds);
    o.z = dec1((nib >>  8) & 15u, ds);
    o.w = dec1((nib >> 12) & 15u, ds);

    if (e0 + 4 <= (long)n) {
        reinterpret_cast<float4*>(out)[p4] = o;
    } else {
        out[e0] = o.x;
        if (e0 + 1 < (long)n) out[e0 + 1] = o.y;
        if (e0 + 2 < (long)n) out[e0 + 2] = o.z;
    }
}

extern "C" void kernel_launch(void* const* d_in, const int* in_sizes, int n_in,
                              void* d_out, int out_size) {
    const float* x = (const float*)d_in[0];
    int n = in_sizes[0];
    int nblocks = (n + 63) / 64;
    int grid1 = (nblocks + BLK_PER_CTA - 1) / BLK_PER_CTA;
    int gridb = (nblocks + 255) / 256;
    int n4 = (n + 3) / 4;
    int grid2 = (n4 + 255) / 256;

    k_init<<<1, 1>>>();
    k_pass1<<<grid1, P1_THREADS>>>(x, nblocks, n);
    k_ds<<<gridb, 256>>>(nblocks);
    k_pass2<<<grid2, 256>>>((float*)d_out, n);
}

// round 4
// speedup vs baseline: 1.6808x; 1.1433x over previous
#include <cuda_runtime.h>
#include <cstdint>

// ---------------------------------------------------------------------------
// FP4 block quant-dequant, BLOCK=64, scale = 95th pct of |x| per block,
// double-quantized scales (global min/max over blocks).
//
//   k_init  : reset global scale min/max                (every replay)
//   k_pass1 : TMA bulk load -> smem -> regs (single read, rotated,
//             conflict-free); top-5 + premultiplied-threshold quantize
//   k_ds    : per-block dequant scale ds = q*ss
//   k_pass2 : codes -> output, 2 float4/thread, MLP 4, streaming stores
// ---------------------------------------------------------------------------

#define NBLK_CAP 262144   // 16777216 / 64
#define P1_THREADS 128
#define BLK_PER_CTA 128   // one 64-elt block per thread

__device__ float    g_scales[NBLK_CAP];
__device__ float    g_ds[NBLK_CAP];
__device__ unsigned g_codes32[NBLK_CAP * 8];  // 8 u32 per block, element order
__device__ unsigned g_smin_bits;
__device__ unsigned g_smax_bits;

__global__ void k_init() {
    g_smin_bits = 0x7F800000u;  // +inf
    g_smax_bits = 0u;
}

// ---- minimal mbarrier / bulk-copy PTX helpers ----
__device__ __forceinline__ unsigned smem_u32(const void* p) {
    return (unsigned)__cvta_generic_to_shared(p);
}
__device__ __forceinline__ void mbar_init(unsigned a, unsigned cnt) {
    asm volatile("mbarrier.init.shared.b64 [%0], %1;" :: "r"(a), "r"(cnt) : "memory");
}
__device__ __forceinline__ void mbar_expect_tx(unsigned a, unsigned bytes) {
    asm volatile("mbarrier.arrive.expect_tx.shared.b64 _, [%0], %1;"
                 :: "r"(a), "r"(bytes) : "memory");
}
__device__ __forceinline__ void bulk_g2s(unsigned dst, const void* src,
                                         unsigned bytes, unsigned mbar) {
    asm volatile(
        "cp.async.bulk.shared::cta.global.mbarrier::complete_tx::bytes "
        "[%0], [%1], %2, [%3];"
        :: "r"(dst), "l"(src), "r"(bytes), "r"(mbar) : "memory");
}
__device__ __forceinline__ void mbar_wait(unsigned a, unsigned phase) {
    asm volatile(
        "{\n\t"
        ".reg .pred P;\n\t"
        "WL%=:\n\t"
        "mbarrier.try_wait.parity.acquire.cta.shared::cta.b64 P, [%0], %1;\n\t"
        "@!P bra WL%=;\n\t"
        "}"
        :: "r"(a), "r"(phase) : "memory");
}

// Branchless insert of v (>=0) into descending top-5 (t0 >= ... >= t4).
__device__ __forceinline__ void ins5(float& t0, float& t1, float& t2,
                                     float& t3, float& t4, float v) {
    float a;
    a = fminf(t0, v); t0 = fmaxf(t0, v);
    float b = fminf(t1, a); t1 = fmaxf(t1, a);
    a = fminf(t2, b); t2 = fmaxf(t2, b);
    b = fminf(t3, a); t3 = fmaxf(t3, a);
    t4 = fmaxf(t4, b);
}

// Quantize vs per-block premultiplied midpoints C[5] (uint bits of
// s*{0.375,0.875,1.25,1.75,2.5}); uint compare == float compare for
// positives. Code: bit3 = sign, bits[2:0] = level 0..5.
__device__ __forceinline__ unsigned quant1(float xx, const unsigned* C) {
    unsigned bits = __float_as_uint(xx);
    unsigned mag  = bits & 0x7FFFFFFFu;
    unsigned k = (unsigned)(mag > C[0]) + (unsigned)(mag > C[1])
               + (unsigned)(mag > C[2]) + (unsigned)(mag > C[3])
               + (unsigned)(mag > C[4]);
    return k | ((bits >> 28) & 8u);
}

__global__ void __launch_bounds__(P1_THREADS) k_pass1(const float* __restrict__ x,
                                                      int nblocks, int n) {
    __shared__ __align__(16) float4 sm[BLK_PER_CTA * 16];  // 32 KB
    __shared__ __align__(8) unsigned long long mbar;

    int tid = threadIdx.x;
    long cta_blk0 = (long)blockIdx.x * BLK_PER_CTA;
    long e_base = cta_blk0 * 64;
    bool full = e_base + BLK_PER_CTA * 64 <= (long)n;

    if (full) {
        if (tid == 0) mbar_init(smem_u32(&mbar), 1);
        __syncthreads();
        if (tid == 0) {
            unsigned mb = smem_u32(&mbar);
            mbar_expect_tx(mb, BLK_PER_CTA * 256);
            bulk_g2s(smem_u32(sm), x + e_base, BLK_PER_CTA * 256, mb);
        }
        mbar_wait(smem_u32(&mbar), 0);
    } else {
        #pragma unroll
        for (int k = 0; k < 16; k++) {
            int l4 = tid + k * P1_THREADS;
            long e = e_base + (long)l4 * 4;
            float4 v;
            v.x = (e + 0 < (long)n) ? x[e + 0] : 0.0f;
            v.y = (e + 1 < (long)n) ? x[e + 1] : 0.0f;
            v.z = (e + 2 < (long)n) ? x[e + 2] : 0.0f;
            v.w = (e + 3 < (long)n) ? x[e + 3] : 0.0f;
            sm[l4] = v;
        }
        __syncthreads();
    }

    long b = cta_blk0 + tid;
    bool valid = b < (long)nblocks;
    float vmn = __uint_as_float(0x7F800000u);
    float vmx = 0.0f;

    if (valid) {
        // single smem read, rotated (conflict-free), register-resident
        float4 vals[16];
        #pragma unroll
        for (int i = 0; i < 16; i++)
            vals[i] = sm[(tid << 4) | ((i + tid) & 15)];

        // ---- top-5 of |x| ----
        float t0 = 0.f, t1 = 0.f, t2 = 0.f, t3 = 0.f, t4 = 0.f;
        #pragma unroll
        for (int i = 0; i < 16; i++) {
            ins5(t0, t1, t2, t3, t4, fabsf(vals[i].x));
            ins5(t0, t1, t2, t3, t4, fabsf(vals[i].y));
            ins5(t0, t1, t2, t3, t4, fabsf(vals[i].z));
            ins5(t0, t1, t2, t3, t4, fabsf(vals[i].w));
        }

        // 95th pct linear interp: idx = 0.95*63 between sorted[59]=t4,
        // sorted[60]=t3.
        const float idxf = 0.95f * 63.0f;
        const float hw   = idxf - 59.0f;
        const float lw   = 1.0f - hw;
        float s = t4 * lw + t3 * hw;
        s = fmaxf(s, 1e-8f);
        g_scales[b] = s;
        vmn = s; vmx = s;

        unsigned C[5];
        C[0] = __float_as_uint(s * 0.375f);
        C[1] = __float_as_uint(s * 0.875f);
        C[2] = __float_as_uint(s * 1.25f);
        C[3] = __float_as_uint(s * 1.75f);
        C[4] = __float_as_uint(s * 2.5f);

        // ---- quantize + pack (undo rotation when placing nibbles) ----
        unsigned w[8];
        #pragma unroll
        for (int i = 0; i < 8; i++) w[i] = 0u;
        #pragma unroll
        for (int i = 0; i < 16; i++) {
            int j = (i + tid) & 15;   // true float4 position in block
            unsigned nib =  quant1(vals[i].x, C)
                         | (quant1(vals[i].y, C) << 4)
                         | (quant1(vals[i].z, C) << 8)
                         | (quant1(vals[i].w, C) << 12);
            w[j >> 1] |= nib << ((j & 1) * 16);
        }
        uint4* c4 = reinterpret_cast<uint4*>(g_codes32);
        c4[(size_t)b * 2 + 0] = make_uint4(w[0], w[1], w[2], w[3]);
        c4[(size_t)b * 2 + 1] = make_uint4(w[4], w[5], w[6], w[7]);
    }

    // warp + CTA reduce of scale min/max, one atomic pair per CTA
    #pragma unroll
    for (int o = 16; o > 0; o >>= 1) {
        vmn = fminf(vmn, __shfl_xor_sync(0xFFFFFFFFu, vmn, o));
        vmx = fmaxf(vmx, __shfl_xor_sync(0xFFFFFFFFu, vmx, o));
    }
    __shared__ float shm[4], shx[4];
    int wid = tid >> 5;
    if ((tid & 31) == 0) { shm[wid] = vmn; shx[wid] = vmx; }
    __syncthreads();
    if (tid == 0) {
        float mn = shm[0], mx = shx[0];
        #pragma unroll
        for (int i = 1; i < 4; i++) {
            mn = fminf(mn, shm[i]);
            mx = fmaxf(mx, shx[i]);
        }
        atomicMin(&g_smin_bits, __float_as_uint(mn));
        atomicMax(&g_smax_bits, __float_as_uint(mx));
    }
}

// Per-block dequant scale: ds = round((s-smin)/ss) * ss, ss = (smax-smin)/255.
// (Reference drops smin in dequant — faithful.)
__global__ void __launch_bounds__(256) k_ds(int nblocks) {
    int b = blockIdx.x * 256 + threadIdx.x;
    if (b >= nblocks) return;
    float smin = __uint_as_float(g_smin_bits);
    float smax = __uint_as_float(g_smax_bits);
    bool cond = smax > smin;
    float ss  = cond ? (smax - smin) / 255.0f : 1.0f;
    float iss = 1.0f / ss;
    float s = g_scales[b];
    float d  = s - smin;
    float q0 = d * iss;
    float q  = fmaf(fmaf(-ss, q0, d), iss, q0);  // refined == fl(d/ss)
    q = rintf(q);                                // half-to-even == jnp.round
    q = fminf(fmaxf(q, 0.0f), 255.0f);
    if (!cond) q = 0.0f;
    g_ds[b] = q * ss;
}

// Decode 4-bit code: magnitudes {0,0.75,1,1.5,2,3} linear in fp32 bits:
// eb = 0x3F000000 + (k<<22) for k>0; bit3 -> sign.
__device__ __forceinline__ float dec1(unsigned c, float ds) {
    unsigned k  = c & 7u;
    unsigned eb = 0x3F000000u + (k << 22);
    eb = k ? eb : 0u;
    eb |= (c & 8u) << 28;
    return __uint_as_float(eb) * ds;
}

__device__ __forceinline__ float4 dec4(unsigned nib, float ds) {
    float4 o;
    o.x = dec1( nib        & 15u, ds);
    o.y = dec1((nib >>  4) & 15u, ds);
    o.z = dec1((nib >>  8) & 15u, ds);
    o.w = dec1((nib >> 12) & 15u, ds);
    return o;
}

__global__ void __launch_bounds__(256) k_pass2(float* __restrict__ out, int n) {
    int n4 = (n + 3) >> 2;
    int f0 = blockIdx.x * 512 + threadIdx.x;
    int f1 = f0 + 256;
    bool v0 = f0 < n4, v1 = f1 < n4;

    // issue all loads up front (MLP 4)
    unsigned cw0 = 0, cw1 = 0;
    float ds0 = 0.f, ds1 = 0.f;
    if (v0) { cw0 = g_codes32[f0 >> 1]; ds0 = g_ds[f0 >> 4]; }
    if (v1) { cw1 = g_codes32[f1 >> 1]; ds1 = g_ds[f1 >> 4]; }

    if (v0) {
        float4 o = dec4(cw0 >> ((f0 & 1) * 16), ds0);
        long e0 = (long)f0 * 4;
        if (e0 + 4 <= (long)n) {
            __stcs(reinterpret_cast<float4*>(out) + f0, o);
        } else {
            out[e0] = o.x;
            if (e0 + 1 < (long)n) out[e0 + 1] = o.y;
            if (e0 + 2 < (long)n) out[e0 + 2] = o.z;
        }
    }
    if (v1) {
        float4 o = dec4(cw1 >> ((f1 & 1) * 16), ds1);
        long e0 = (long)f1 * 4;
        if (e0 + 4 <= (long)n) {
            __stcs(reinterpret_cast<float4*>(out) + f1, o);
        } else {
            out[e0] = o.x;
            if (e0 + 1 < (long)n) out[e0 + 1] = o.y;
            if (e0 + 2 < (long)n) out[e0 + 2] = o.z;
        }
    }
}

extern "C" void kernel_launch(void* const* d_in, const int* in_sizes, int n_in,
                              void* d_out, int out_size) {
    const float* x = (const float*)d_in[0];
    int n = in_sizes[0];
    int nblocks = (n + 63) / 64;
    int grid1 = (nblocks + BLK_PER_CTA - 1) / BLK_PER_CTA;
    int gridb = (nblocks + 255) / 256;
    int n4 = (n + 3) / 4;
    int grid2 = (n4 + 511) / 512;

    k_init<<<1, 1>>>();
    k_pass1<<<grid1, P1_THREADS>>>(x, nblocks, n);
    k_ds<<<gridb, 256>>>(nblocks);
    k_pass2<<<grid2, 256>>>((float*)d_out, n);
}